// round 9
// baseline (speedup 1.0000x reference)
#include <cuda_runtime.h>
#include <cuda_bf16.h>

// y[b,n] = x[b,n] * W[n],  W[n] = sum over valid frames m of aw[j]*sw[j],
// j = (n mod 256) + 256*m, m in [max(0, q-8188), min(3, q)], q = n/256.
//
// Launch geometry: 2048 blocks x 256 threads = 524,288 threads = exactly one
// row of float4s (N4ROW). Thread t owns float4 index `base` in EVERY row;
// its sample phase is fixed, so W (incl. boundary truncation) is a
// per-thread constant.
//
// Body: depth-4 RING pipeline. Each iteration stores one row and issues the
// load 4 rows ahead -> per-warp outstanding loads are a constant 4, with a
// strict 1:1 load/store interleave (no burst phases), presenting the
// smoothest mixed r/w stream to HBM.

#define HOPC      256u
#define NSAMP     (1u << 21)          // samples per row
#define NROWS     16u
#define QMAXV     8188u               // num_segments - 1
#define N4ROW     (NSAMP / 4u)        // 524,288 float4 per row
#define NBLK      2048u
#define NTHR      256u
#define DEPTH     4u                  // ring depth

__global__ void __launch_bounds__(NTHR, 5)
segmenter_roundtrip_kernel(const float4* __restrict__ x,
                           const float4* __restrict__ aw4,
                           const float4* __restrict__ sw4,
                           float4*       __restrict__ y) {
    const unsigned base = blockIdx.x * NTHR + threadIdx.x;  // f4 idx in row

    const unsigned n  = base << 2;               // sample index within row
    const unsigned q  = n >> 8;                  // frame-phase index
    const unsigned r4 = (n & (HOPC - 1u)) >> 2;  // float4 index of r

    // Truncated frame range (interior: [0,3]).
    const int m_lo = (q > QMAXV) ? (int)(q - QMAXV) : 0;
    const int m_hi = (q < 3u) ? (int)q : 3;

    // Per-thread weights: 8 vector loads total (windows L1/L2-hot).
    float w0 = 0.f, w1 = 0.f, w2 = 0.f, w3 = 0.f;
#pragma unroll
    for (int m = 0; m < 4; ++m) {
        const float mask = (m >= m_lo && m <= m_hi) ? 1.0f : 0.0f;
        const float4 a = aw4[r4 + (unsigned)m * (HOPC / 4u)];
        const float4 s = sw4[r4 + (unsigned)m * (HOPC / 4u)];
        w0 += mask * a.x * s.x;
        w1 += mask * a.y * s.y;
        w2 += mask * a.z * s.z;
        w3 += mask * a.w * s.w;
    }

    // ---- Prime the ring: rows 0..3 in flight ----
    float4 v[DEPTH];
#pragma unroll
    for (unsigned k = 0; k < DEPTH; ++k)
        v[k] = __ldcg(&x[k * N4ROW + base]);

    // ---- Steady state: store row k, load row k+4 into the freed slot ----
#pragma unroll
    for (unsigned k = 0; k < NROWS; ++k) {
        const unsigned s = k & (DEPTH - 1u);
        float4 t = v[s];
        if (k + DEPTH < NROWS)
            v[s] = __ldcg(&x[(k + DEPTH) * N4ROW + base]);
        t.x *= w0; t.y *= w1; t.z *= w2; t.w *= w3;
        __stcg(&y[k * N4ROW + base], t);
    }
}

extern "C" void kernel_launch(void* const* d_in, const int* in_sizes, int n_in,
                              void* d_out, int out_size) {
    const float4* x  = (const float4*)d_in[0];
    const float4* aw = (const float4*)d_in[1];
    const float4* sw = (const float4*)d_in[2];
    float4*       y  = (float4*)d_out;

    (void)in_sizes; (void)n_in; (void)out_size;

    segmenter_roundtrip_kernel<<<NBLK, NTHR>>>(x, aw, sw, y);
}